// round 7
// baseline (speedup 1.0000x reference)
#include <cuda_runtime.h>
#include <cuda_bf16.h>

// Problem constants
#define BB 8
#define NN 512
#define DD 64
#define EE 32

#define JT 32                 // edge: j's per block
#define JR 4                  // edge: j's per warp (2 f32x2 pairs)
#define SS 8                  // i-splits
#define IT (NN / SS)          // 64 i-rows per block

#define RPB 16                // proj: x-rows per block
#define RPW 4                 // proj: rows per warp

// Scratch (allocation-free rule -> __device__ globals)
__device__ float g_src [BB * NN * EE];        // src[b,n,e]
__device__ float g_dstb[BB * NN * EE];        // dst[b,n,e] + be[e]
__device__ float g_part[BB * NN * SS];        // partial[b,j,s]

// ---- packed fp32 pair helpers (sm_103a FADD2/FFMA2 via PTX f32x2) ----------
union F2U { unsigned long long u; float2 f; };

__device__ __forceinline__ unsigned long long add2(unsigned long long a,
                                                   unsigned long long b) {
    unsigned long long r;
    asm("add.rn.f32x2 %0, %1, %2;" : "=l"(r) : "l"(a), "l"(b));
    return r;
}
__device__ __forceinline__ unsigned long long fma2(unsigned long long a,
                                                   unsigned long long b,
                                                   unsigned long long c) {
    unsigned long long r;
    asm("fma.rn.f32x2 %0, %1, %2, %3;" : "=l"(r) : "l"(a), "l"(b), "l"(c));
    return r;
}

// ---------------------------------------------------------------------------
// Kernel 1 (R4 config): src = x @ We[:D], dstb = x @ We[D:] + be
// 256 blocks, 256 threads, 16 rows/block; warps 0-3 src half, 4-7 dst half.
// ---------------------------------------------------------------------------
__global__ __launch_bounds__(256) void proj_kernel(
    const float* __restrict__ x,
    const float* __restrict__ We,
    const float* __restrict__ be)
{
    const int row0 = blockIdx.x * RPB;          // first (b*N+n) row
    __shared__ float xs [RPB][DD];              // 4 KB
    __shared__ float Wsh[2 * DD][EE];           // 16 KB

    const int tid = threadIdx.x;
    #pragma unroll
    for (int k = 0; k < 4; k++)
        ((float4*)Wsh)[k * 256 + tid] = ((const float4*)We)[k * 256 + tid];
    ((float4*)xs)[tid] = ((const float4*)(x + row0 * DD))[tid];
    __syncthreads();

    const int lane = tid & 31;                  // = e
    const int w    = tid >> 5;
    const int half = w >> 2;                    // 0 = src, 1 = dst
    const int r0   = (w & 3) * RPW;             // 4 rows per warp

    const float* Wh = &Wsh[half * DD][0];
    const float bias = half ? be[lane] : 0.0f;

    float acc[RPW];
    #pragma unroll
    for (int r = 0; r < RPW; r++) acc[r] = bias;

    #pragma unroll
    for (int d4 = 0; d4 < DD; d4 += 4) {
        float4 xv[RPW];
        #pragma unroll
        for (int r = 0; r < RPW; r++)
            xv[r] = *(const float4*)&xs[r0 + r][d4];  // broadcast LDS.128
        #pragma unroll
        for (int k = 0; k < 4; k++) {
            float wv = Wh[(d4 + k) * EE + lane];      // conflict-free LDS
            #pragma unroll
            for (int r = 0; r < RPW; r++)
                acc[r] = fmaf((&xv[r].x)[k], wv, acc[r]);
        }
    }

    float* dst = half ? g_dstb : g_src;
    #pragma unroll
    for (int r = 0; r < RPW; r++)
        dst[(row0 + r0 + r) * EE + lane] = acc[r];
}

// ---------------------------------------------------------------------------
// Kernel 2: partial[b,j,s] = sum_{i in tile s, e} relu(src+dstb)*Wr
// f32x2: j-pairs packed; src/Wr staged PRE-DUPLICATED (v,v) so one LDS.64
// yields a broadcast-packed operand. Per i: 2 LDS.64 + 2 ADD2 + 4 FMNMX + 2 FFMA2.
// Grid: (N/32, B, 8) = 1024 blocks, 256 threads.
// ---------------------------------------------------------------------------
__global__ __launch_bounds__(256) void edge_reduce_kernel(
    const float* __restrict__ Wr,
    float* __restrict__ part)
{
    const int b  = blockIdx.y;
    const int jb = blockIdx.x;
    const int s  = blockIdx.z;
    const int tid  = threadIdx.x;
    const int lane = tid & 31;                  // = e
    const int w    = tid >> 5;                  // warp 0..7

    __shared__ float2 src2_sh[IT * EE];         // 16 KB, duplicated pairs
    __shared__ float2 wr2_sh [IT * EE];         // 16 KB, duplicated pairs
    __shared__ float  dst_sh [JT * EE];         // 4 KB

    // stage: dst scalar (1 float4/thread); src/Wr duplicated (v.x,v.x,v.y,v.y)...
    {
        const float4* dst_g = (const float4*)(g_dstb + (b * NN + jb * JT) * EE);
        ((float4*)dst_sh)[tid] = dst_g[tid];

        const float4* src_g = (const float4*)(g_src + (b * NN + s * IT) * EE);
        const float4* wr_g  = (const float4*)(Wr + s * IT * EE);
        float4* s2 = (float4*)src2_sh;
        float4* w2 = (float4*)wr2_sh;
        #pragma unroll
        for (int k = 0; k < 2; k++) {           // 512 float4 per array
            const int j = k * 256 + tid;
            float4 v = src_g[j];
            s2[2*j]   = make_float4(v.x, v.x, v.y, v.y);
            s2[2*j+1] = make_float4(v.z, v.z, v.w, v.w);
            float4 u = wr_g[j];
            w2[2*j]   = make_float4(u.x, u.x, u.y, u.y);
            w2[2*j+1] = make_float4(u.z, u.z, u.w, u.w);
        }
    }
    __syncthreads();

    // dreg pairs: pair p holds (dstb[j0], dstb[j1]) for j0 = w*JR+2p, j1 = j0+1
    F2U dreg2[JR/2], acc2[JR/2];
    #pragma unroll
    for (int p = 0; p < JR/2; p++) {
        dreg2[p].f.x = dst_sh[(w * JR + 2*p    ) * EE + lane];
        dreg2[p].f.y = dst_sh[(w * JR + 2*p + 1) * EE + lane];
        acc2[p].u = 0ull;
    }

    #pragma unroll 8
    for (int i = 0; i < IT; i++) {
        F2U sv2, wv2;
        sv2.f = src2_sh[i * EE + lane];         // LDS.64, (sv,sv)
        wv2.f = wr2_sh [i * EE + lane];         // LDS.64, (wv,wv)
        #pragma unroll
        for (int p = 0; p < JR/2; p++) {
            F2U t; t.u = add2(sv2.u, dreg2[p].u);      // FADD2
            t.f.x = fmaxf(t.f.x, 0.0f);                // FMNMX (alu pipe)
            t.f.y = fmaxf(t.f.y, 0.0f);
            acc2[p].u = fma2(t.u, wv2.u, acc2[p].u);   // FFMA2
        }
    }

    // unpack and reduce across lanes (e dim + per-lane partial i-sums)
    float acc[JR];
    #pragma unroll
    for (int p = 0; p < JR/2; p++) {
        acc[2*p]     = acc2[p].f.x;
        acc[2*p + 1] = acc2[p].f.y;
    }
    #pragma unroll
    for (int r = 0; r < JR; r++) {
        #pragma unroll
        for (int off = 16; off; off >>= 1)
            acc[r] += __shfl_xor_sync(0xFFFFFFFFu, acc[r], off);
    }

    if (lane == 0) {
        const int j = jb * JT + w * JR;
        #pragma unroll
        for (int r = 0; r < JR; r++)
            part[(b * NN + j + r) * SS + s] = acc[r];
    }
}

// ---------------------------------------------------------------------------
// Kernel 3: out[b,j] = sum_s partial[b,j,s] + br
// ---------------------------------------------------------------------------
__global__ __launch_bounds__(256) void final_reduce_kernel(
    const float* __restrict__ part,
    const float* __restrict__ br,
    float* __restrict__ out)
{
    const int idx = blockIdx.x * 256 + threadIdx.x;   // b*N + j, 0..4095
    const float4* p = (const float4*)(part + idx * SS);
    float4 a = p[0];
    float4 c = p[1];
    out[idx] = (a.x + a.y) + (a.z + a.w) + (c.x + c.y) + (c.z + c.w) + br[0];
}

// ---------------------------------------------------------------------------
// launch
// ---------------------------------------------------------------------------
extern "C" void kernel_launch(void* const* d_in, const int* in_sizes, int n_in,
                              void* d_out, int out_size)
{
    const float* x  = (const float*)d_in[0];   // (8,512,64)
    const float* We = (const float*)d_in[1];   // (128,32)
    const float* be = (const float*)d_in[2];   // (32,)
    const float* Wr = (const float*)d_in[3];   // (16384,1)
    const float* br = (const float*)d_in[4];   // (1,)
    float* out = (float*)d_out;                // (8,512,1)

    float* partp;
    cudaGetSymbolAddress((void**)&partp, g_part);

    proj_kernel<<<BB * NN / RPB, 256>>>(x, We, be);

    dim3 grid(NN / JT, BB, SS);
    edge_reduce_kernel<<<grid, 256>>>(Wr, partp);

    final_reduce_kernel<<<BB * NN / 256, 256>>>(partp, br, out);
}

// round 8
// speedup vs baseline: 1.6514x; 1.6514x over previous
#include <cuda_runtime.h>
#include <cuda_bf16.h>

// Problem constants
#define BB 8
#define NN 512
#define DD 64
#define EE 32

#define JT 64                 // edge: j's per block (8 warps x 8 j)
#define SS 8                  // i-splits
#define IT (NN / SS)          // 64 i-rows per block

#define RPB 16                // proj: x-rows per block
#define RPW 4                 // proj: rows per warp

// Scratch (allocation-free rule -> __device__ globals)
__device__ float g_src [BB * NN * EE];        // src[b,n,e]
__device__ float g_dstb[BB * NN * EE];        // dst[b,n,e] + be[e]
__device__ float g_part[BB * NN * SS];        // partial[b,j,s]

// ---- packed fp32 pair helpers (sm_103a FADD2/FFMA2 via PTX f32x2) ----------
union F2U { unsigned long long u; float2 f; };

__device__ __forceinline__ unsigned long long add2(unsigned long long a,
                                                   unsigned long long b) {
    unsigned long long r;
    asm("add.rn.f32x2 %0, %1, %2;" : "=l"(r) : "l"(a), "l"(b));
    return r;
}
__device__ __forceinline__ unsigned long long fma2(unsigned long long a,
                                                   unsigned long long b,
                                                   unsigned long long c) {
    unsigned long long r;
    asm("fma.rn.f32x2 %0, %1, %2, %3;" : "=l"(r) : "l"(a), "l"(b), "l"(c));
    return r;
}

// ---------------------------------------------------------------------------
// Kernel 1 (R4 exact): src = x @ We[:D], dstb = x @ We[D:] + be
// 256 blocks, 256 threads, 16 rows/block; warps 0-3 src half, 4-7 dst half.
// ---------------------------------------------------------------------------
__global__ __launch_bounds__(256) void proj_kernel(
    const float* __restrict__ x,
    const float* __restrict__ We,
    const float* __restrict__ be)
{
    const int row0 = blockIdx.x * RPB;          // first (b*N+n) row
    __shared__ float xs [RPB][DD];              // 4 KB
    __shared__ float Wsh[2 * DD][EE];           // 16 KB

    const int tid = threadIdx.x;
    #pragma unroll
    for (int k = 0; k < 4; k++)
        ((float4*)Wsh)[k * 256 + tid] = ((const float4*)We)[k * 256 + tid];
    ((float4*)xs)[tid] = ((const float4*)(x + row0 * DD))[tid];
    __syncthreads();

    const int lane = tid & 31;                  // = e
    const int w    = tid >> 5;
    const int half = w >> 2;                    // 0 = src, 1 = dst
    const int r0   = (w & 3) * RPW;             // 4 rows per warp

    const float* Wh = &Wsh[half * DD][0];
    const float bias = half ? be[lane] : 0.0f;

    float acc[RPW];
    #pragma unroll
    for (int r = 0; r < RPW; r++) acc[r] = bias;

    #pragma unroll
    for (int d4 = 0; d4 < DD; d4 += 4) {
        float4 xv[RPW];
        #pragma unroll
        for (int r = 0; r < RPW; r++)
            xv[r] = *(const float4*)&xs[r0 + r][d4];  // broadcast LDS.128
        #pragma unroll
        for (int k = 0; k < 4; k++) {
            float wv = Wh[(d4 + k) * EE + lane];      // conflict-free LDS
            #pragma unroll
            for (int r = 0; r < RPW; r++)
                acc[r] = fmaf((&xv[r].x)[k], wv, acc[r]);
        }
    }

    float* dst = half ? g_dstb : g_src;
    #pragma unroll
    for (int r = 0; r < RPW; r++)
        dst[(row0 + r0 + r) * EE + lane] = acc[r];
}

// ---------------------------------------------------------------------------
// Kernel 2: partial[b,j,s] = sum_{i in tile s, e} relu(src+dstb)*Wr
// f32x2 packed over the E dimension (natural float2 contiguity, no duplication).
// 16 lanes = e-pairs; half-warps take different j-groups; warp owns 8 j's.
// Grid: (N/64, B, 8) = 512 blocks, 256 threads.
// ---------------------------------------------------------------------------
__global__ __launch_bounds__(256) void edge_reduce_kernel(
    const float* __restrict__ Wr,
    float* __restrict__ part)
{
    const int b  = blockIdx.y;
    const int jb = blockIdx.x;
    const int s  = blockIdx.z;
    const int tid  = threadIdx.x;
    const int lane = tid & 31;
    const int w    = tid >> 5;                  // warp 0..7
    const int le   = lane & 15;                 // e-pair index (e = 2*le)
    const int jg   = lane >> 4;                 // j-group within warp (0/1)

    __shared__ float src_sh[IT * EE];           // 8 KB
    __shared__ float wr_sh [IT * EE];           // 8 KB
    __shared__ float dst_sh[JT * EE];           // 8 KB

    // stage tiles, float4 coalesced, 2 per thread per array (R4 pattern)
    {
        const float4* dst_g = (const float4*)(g_dstb + (b * NN + jb * JT) * EE);
        const float4* src_g = (const float4*)(g_src  + (b * NN + s  * IT) * EE);
        const float4* wr_g  = (const float4*)(Wr + s * IT * EE);
        #pragma unroll
        for (int k = 0; k < 2; k++) {
            ((float4*)dst_sh)[k * 256 + tid] = dst_g[k * 256 + tid];
            ((float4*)src_sh)[k * 256 + tid] = src_g[k * 256 + tid];
            ((float4*)wr_sh )[k * 256 + tid] = wr_g [k * 256 + tid];
        }
    }
    __syncthreads();

    // this thread's 4 j's: j_local = w*8 + jg*4 + r
    const int jl0 = w * 8 + jg * 4;
    F2U dreg2[4], acc2[4];
    #pragma unroll
    for (int r = 0; r < 4; r++) {
        dreg2[r].f = *(const float2*)&dst_sh[(jl0 + r) * EE + 2 * le];
        acc2[r].u  = 0ull;
    }

    #pragma unroll 8
    for (int i = 0; i < IT; i++) {
        F2U sv2, wv2;
        sv2.f = *(const float2*)&src_sh[i * EE + 2 * le];  // LDS.64, half-warp bcast
        wv2.f = *(const float2*)&wr_sh [i * EE + 2 * le];
        #pragma unroll
        for (int r = 0; r < 4; r++) {
            F2U t; t.u = add2(sv2.u, dreg2[r].u);          // FADD2
            t.f.x = fmaxf(t.f.x, 0.0f);                    // FMNMX (alu pipe)
            t.f.y = fmaxf(t.f.y, 0.0f);
            acc2[r].u = fma2(t.u, wv2.u, acc2[r].u);       // FFMA2
        }
    }

    // collapse e-pair, then reduce over the 16 lanes of each half-warp
    float acc[4];
    #pragma unroll
    for (int r = 0; r < 4; r++) {
        acc[r] = acc2[r].f.x + acc2[r].f.y;
        #pragma unroll
        for (int off = 8; off; off >>= 1)
            acc[r] += __shfl_xor_sync(0xFFFFFFFFu, acc[r], off);
    }

    if (le == 0) {                              // lanes 0 and 16 write
        const int j = jb * JT + jl0;
        #pragma unroll
        for (int r = 0; r < 4; r++)
            part[(b * NN + j + r) * SS + s] = acc[r];
    }
}

// ---------------------------------------------------------------------------
// Kernel 3: out[b,j] = sum_s partial[b,j,s] + br
// ---------------------------------------------------------------------------
__global__ __launch_bounds__(256) void final_reduce_kernel(
    const float* __restrict__ part,
    const float* __restrict__ br,
    float* __restrict__ out)
{
    const int idx = blockIdx.x * 256 + threadIdx.x;   // b*N + j, 0..4095
    const float4* p = (const float4*)(part + idx * SS);
    float4 a = p[0];
    float4 c = p[1];
    out[idx] = (a.x + a.y) + (a.z + a.w) + (c.x + c.y) + (c.z + c.w) + br[0];
}

// ---------------------------------------------------------------------------
// launch
// ---------------------------------------------------------------------------
extern "C" void kernel_launch(void* const* d_in, const int* in_sizes, int n_in,
                              void* d_out, int out_size)
{
    const float* x  = (const float*)d_in[0];   // (8,512,64)
    const float* We = (const float*)d_in[1];   // (128,32)
    const float* be = (const float*)d_in[2];   // (32,)
    const float* Wr = (const float*)d_in[3];   // (16384,1)
    const float* br = (const float*)d_in[4];   // (1,)
    float* out = (float*)d_out;                // (8,512,1)

    float* partp;
    cudaGetSymbolAddress((void**)&partp, g_part);

    proj_kernel<<<BB * NN / RPB, 256>>>(x, We, be);

    dim3 grid(NN / JT, BB, SS);
    edge_reduce_kernel<<<grid, 256>>>(Wr, partp);

    final_reduce_kernel<<<BB * NN / 256, 256>>>(partp, br, out);
}